// round 8
// baseline (speedup 1.0000x reference)
#include <cuda_runtime.h>
#include <cuda_fp16.h>
#include <cstdint>
#include <math.h>

#define D 768
#define N_MAX 10000
#define E_RAW_MAX 100000
#define E_TOT_MAX (E_RAW_MAX + N_MAX)

// ---------------- scratch (device globals; no allocation allowed) ----------------
__device__ __half g_h1[(size_t)N_MAX * D];
__device__ __half g_h2[(size_t)N_MAX * D];
__device__ __half g_xh[(size_t)N_MAX * D];
__device__ __half g_gh[(size_t)N_MAX * D];
__device__ __half g_w1h[D * D];
__device__ __half g_w2h[D * D];
__device__ float g_es1[N_MAX], g_ed1[N_MAX];
__device__ float g_es2[N_MAX], g_ed2[N_MAX];
__device__ int   g_off[N_MAX + 1];
__device__ int   g_cur[N_MAX];
__device__ int   g_csr_src[E_TOT_MAX];
__device__ int   g_csr_dst[E_TOT_MAX];
__device__ float g_wbuf[E_TOT_MAX];

// ================= helpers =================
__device__ __forceinline__ uint32_t smem_u32(const void* p) {
    uint32_t a;
    asm("{ .reg .u64 t; cvta.to.shared.u64 t, %1; cvt.u32.u64 %0, t; }" : "=r"(a) : "l"(p));
    return a;
}
__device__ __forceinline__ uint32_t sw128(uint32_t x) { return x ^ ((x >> 3) & 0x70); }

__device__ __forceinline__ void cp_async16(uint32_t dst, const void* src) {
    asm volatile("cp.async.cg.shared.global [%0], [%1], 16;" :: "r"(dst), "l"(src) : "memory");
}
__device__ __forceinline__ void ldsm4(uint32_t* r, uint32_t addr) {
    asm volatile("ldmatrix.sync.aligned.m8n8.x4.shared.b16 {%0,%1,%2,%3}, [%4];"
                 : "=r"(r[0]), "=r"(r[1]), "=r"(r[2]), "=r"(r[3]) : "r"(addr));
}
__device__ __forceinline__ void mma_fp16(float* c, const uint32_t* a, const uint32_t* b) {
    asm volatile("mma.sync.aligned.m16n8k16.row.col.f32.f16.f16.f32 "
                 "{%0,%1,%2,%3}, {%4,%5,%6,%7}, {%8,%9}, {%0,%1,%2,%3};"
                 : "+f"(c[0]), "+f"(c[1]), "+f"(c[2]), "+f"(c[3])
                 : "r"(a[0]), "r"(a[1]), "r"(a[2]), "r"(a[3]), "r"(b[0]), "r"(b[1]));
}

// ---------------- zero: cursors + dot accumulators ----------------
__global__ void zero_kernel(int n) {
    int i = blockIdx.x * blockDim.x + threadIdx.x;
    if (i < n) {
        g_cur[i] = 0;
        g_es1[i] = 0.f; g_ed1[i] = 0.f;
        g_es2[i] = 0.f; g_ed2[i] = 0.f;
    }
}
__global__ void hist_kernel(const int* __restrict__ ei, int e_raw, int n) {
    int e = blockIdx.x * blockDim.x + threadIdx.x;
    int e_tot = e_raw + n;
    if (e >= e_tot) return;
    int dst = (e < e_raw) ? ei[e_raw + e] : (e - e_raw);
    atomicAdd(&g_cur[dst], 1);
}
__global__ void scan_kernel(int n) {
    __shared__ int sh[1024];
    __shared__ int s_carry;
    int tid = threadIdx.x;
    if (tid == 0) s_carry = 0;
    __syncthreads();
    for (int base = 0; base < n; base += 1024) {
        int i = base + tid;
        int v = (i < n) ? g_cur[i] : 0;
        sh[tid] = v;
        __syncthreads();
        for (int off = 1; off < 1024; off <<= 1) {
            int t = (tid >= off) ? sh[tid - off] : 0;
            __syncthreads();
            sh[tid] += t;
            __syncthreads();
        }
        int excl = sh[tid] - v;
        int carry = s_carry;
        if (i < n) { g_off[i] = carry + excl; g_cur[i] = carry + excl; }
        __syncthreads();
        if (tid == 1023) s_carry = carry + sh[1023];
        __syncthreads();
    }
    if (tid == 0) g_off[n] = s_carry;
}
__global__ void scatter_kernel(const int* __restrict__ ei, int e_raw, int n) {
    int e = blockIdx.x * blockDim.x + threadIdx.x;
    int e_tot = e_raw + n;
    if (e >= e_tot) return;
    int src = (e < e_raw) ? ei[e]         : (e - e_raw);
    int dst = (e < e_raw) ? ei[e_raw + e] : (e - e_raw);
    int pos = atomicAdd(&g_cur[dst], 1);
    g_csr_src[pos] = src;
    g_csr_dst[pos] = dst;
}

// ---------------- per-edge softmax weight ----------------
__global__ void wcalc_kernel(const float* __restrict__ es, const float* __restrict__ ed,
                             int e_tot) {
    int i = blockIdx.x * blockDim.x + threadIdx.x;
    if (i >= e_tot) return;
    float e = __ldg(&es[g_csr_src[i]]) + __ldg(&ed[g_csr_dst[i]]);
    e = (e > 0.f) ? e : 0.2f * e;
    g_wbuf[i] = expf(e);
}

// ---------------- fp32 -> fp16 ----------------
__global__ void split_kernel(const float* __restrict__ x,
                             __half* __restrict__ xh, int total4) {
    int i = blockIdx.x * blockDim.x + threadIdx.x;
    if (i < total4) {
        float4 v = *(const float4*)(x + i * 4);
        __half2* o = (__half2*)(xh + i * 4);
        o[0] = __floats2half2_rn(v.x, v.y);
        o[1] = __floats2half2_rn(v.z, v.w);
    }
}

// ---------------- W[k][n] -> Wt[n][k] fp16 ----------------
__global__ void transpose_kernel(const float* __restrict__ W,
                                 __half* __restrict__ Th) {
    __shared__ float sh[32][33];
    int n0 = blockIdx.x * 32, k0 = blockIdx.y * 32;
    int tx = threadIdx.x, ty = threadIdx.y;
#pragma unroll
    for (int j = 0; j < 32; j += 8)
        sh[ty + j][tx] = W[(size_t)(k0 + ty + j) * D + n0 + tx];
    __syncthreads();
#pragma unroll
    for (int j = 0; j < 32; j += 8)
        Th[(size_t)(n0 + ty + j) * D + k0 + tx] = __float2half(sh[tx][ty + j]);
}

// ---------------- tensor-core GEMM (fp16, 512 thr / 16 warps) + fused dots --------
// CTA tile 128x128, warp tile 32x32 (4M x 4N warps), K-chunk 64, 3-stage cp.async.
#define STAGE_BYTES 32768
#define GEMM_SMEM (3 * STAGE_BYTES)

__global__ __launch_bounds__(512, 1)
void gemm_mma_kernel(const __half* __restrict__ Ah,
                     const __half* __restrict__ Bh,
                     __half* __restrict__ C,
                     const float* __restrict__ a_src,
                     const float* __restrict__ a_dst,
                     float* __restrict__ es, float* __restrict__ ed,
                     int M) {
    extern __shared__ __align__(1024) char smem[];
    const uint32_t sb = smem_u32(smem);
    const int tid  = threadIdx.x;
    const int wid  = tid >> 5;
    const int lane = tid & 31;
    const int m0 = blockIdx.y * 128;
    const int n0 = blockIdx.x * 128;
    const int warp_m = (wid & 3) * 32;
    const int warp_n = (wid >> 2) * 32;

    float acc[2][4][4];
#pragma unroll
    for (int i = 0; i < 2; i++)
#pragma unroll
        for (int j = 0; j < 4; j++)
#pragma unroll
            for (int k = 0; k < 4; k++) acc[i][j][k] = 0.f;

    auto issue_chunk = [&](int c) {
        const uint32_t st = sb + (uint32_t)(c % 3) * STAGE_BYTES;
        const int kc0 = c * 64;
#pragma unroll
        for (int i = 0; i < 2; i++) {
            int idx = i * 512 + tid;            // 0..1023 granules per matrix
            int row = idx >> 3, cc = idx & 7;
            uint32_t so = sw128((uint32_t)(row * 128 + cc * 16));
            int m = m0 + row; if (m >= M) m = M - 1;   // clamp: rows >= M never stored
            cp_async16(st + 0     + so, Ah + (size_t)m * D + kc0 + cc * 8);
            cp_async16(st + 16384 + so, Bh + (size_t)(n0 + row) * D + kc0 + cc * 8);
        }
    };

    issue_chunk(0);
    asm volatile("cp.async.commit_group;" ::: "memory");
    issue_chunk(1);
    asm volatile("cp.async.commit_group;" ::: "memory");

#pragma unroll 1
    for (int c = 0; c < 12; c++) {
        if (c + 2 < 12) {
            issue_chunk(c + 2);
            asm volatile("cp.async.commit_group;" ::: "memory");
            asm volatile("cp.async.wait_group 2;" ::: "memory");
        } else if (c + 1 < 12) {
            asm volatile("cp.async.wait_group 1;" ::: "memory");
        } else {
            asm volatile("cp.async.wait_group 0;" ::: "memory");
        }
        __syncthreads();

        const uint32_t st = sb + (uint32_t)(c % 3) * STAGE_BYTES;
#pragma unroll
        for (int ks = 0; ks < 4; ks++) {
            uint32_t af[2][4], bf[2][4];
            const int arow = lane & 15;
            const int acol = (ks * 16 + (lane >> 4) * 8) * 2;
#pragma unroll
            for (int mt = 0; mt < 2; mt++) {
                uint32_t off = sw128((uint32_t)((warp_m + mt * 16 + arow) * 128 + acol));
                ldsm4(af[mt], st + off);
            }
            const int brow = (lane & 7) + ((lane >> 4) << 3);
            const int bcol = (ks * 16 + ((lane >> 3) & 1) * 8) * 2;
#pragma unroll
            for (int p = 0; p < 2; p++) {
                uint32_t off = sw128((uint32_t)((warp_n + p * 16 + brow) * 128 + bcol));
                ldsm4(bf[p], st + 16384 + off);
            }
#pragma unroll
            for (int mt = 0; mt < 2; mt++) {
#pragma unroll
                for (int nt = 0; nt < 4; nt++)
                    mma_fp16(acc[mt][nt], af[mt], &bf[nt >> 1][(nt & 1) * 2]);
            }
        }
        __syncthreads();
    }

    // epilogue: store C (fp16) + fused dot partials
    const int er = lane >> 2;
    const int ec = (lane & 3) * 2;
#pragma unroll
    for (int mt = 0; mt < 2; mt++) {
        int row = m0 + warp_m + mt * 16 + er;
        float s0 = 0.f, d0 = 0.f, s1 = 0.f, d1 = 0.f;
#pragma unroll
        for (int nt = 0; nt < 4; nt++) {
            int col = n0 + warp_n + nt * 8 + ec;
            if (row < M)
                *(__half2*)(C + (size_t)row * D + col) =
                    __floats2half2_rn(acc[mt][nt][0], acc[mt][nt][1]);
            if (row + 8 < M)
                *(__half2*)(C + (size_t)(row + 8) * D + col) =
                    __floats2half2_rn(acc[mt][nt][2], acc[mt][nt][3]);
            float as0 = __ldg(a_src + col), as1 = __ldg(a_src + col + 1);
            float ad0 = __ldg(a_dst + col), ad1 = __ldg(a_dst + col + 1);
            s0 = fmaf(acc[mt][nt][0], as0, fmaf(acc[mt][nt][1], as1, s0));
            d0 = fmaf(acc[mt][nt][0], ad0, fmaf(acc[mt][nt][1], ad1, d0));
            s1 = fmaf(acc[mt][nt][2], as0, fmaf(acc[mt][nt][3], as1, s1));
            d1 = fmaf(acc[mt][nt][2], ad0, fmaf(acc[mt][nt][3], ad1, d1));
        }
#pragma unroll
        for (int o = 1; o < 4; o <<= 1) {
            s0 += __shfl_xor_sync(0xffffffffu, s0, o);
            d0 += __shfl_xor_sync(0xffffffffu, d0, o);
            s1 += __shfl_xor_sync(0xffffffffu, s1, o);
            d1 += __shfl_xor_sync(0xffffffffu, d1, o);
        }
        if ((lane & 3) == 0) {
            if (row < M)     { atomicAdd(&es[row],     s0); atomicAdd(&ed[row],     d0); }
            if (row + 8 < M) { atomicAdd(&es[row + 8], s1); atomicAdd(&ed[row + 8], d1); }
        }
    }
}

// ---------------- segment aggregation (weights precomputed, x2 unrolled) ------------
template <int MODE>
__global__ __launch_bounds__(384)
void agg_kernel(const __half* __restrict__ h, const float* __restrict__ bias,
                void* __restrict__ outp) {
    const int node = blockIdx.x;
    const int tid = threadIdx.x;
    const int beg = g_off[node];
    const int end = g_off[node + 1];

    float z0 = 0.f, z1 = 0.f;
    float ax0 = 0.f, ay0 = 0.f, ax1 = 0.f, ay1 = 0.f;
    int i = beg;
    for (; i + 1 < end; i += 2) {
        float w0 = __ldg(&g_wbuf[i]);
        float w1 = __ldg(&g_wbuf[i + 1]);
        int s0 = __ldg(&g_csr_src[i]);
        int s1 = __ldg(&g_csr_src[i + 1]);
        __half2 hv0 = __ldg((const __half2*)(h + (size_t)s0 * D) + tid);
        __half2 hv1 = __ldg((const __half2*)(h + (size_t)s1 * D) + tid);
        z0 += w0; z1 += w1;
        float2 f0 = __half22float2(hv0);
        float2 f1 = __half22float2(hv1);
        ax0 = fmaf(w0, f0.x, ax0); ay0 = fmaf(w0, f0.y, ay0);
        ax1 = fmaf(w1, f1.x, ax1); ay1 = fmaf(w1, f1.y, ay1);
    }
    if (i < end) {
        float w0 = __ldg(&g_wbuf[i]);
        int s0 = __ldg(&g_csr_src[i]);
        __half2 hv0 = __ldg((const __half2*)(h + (size_t)s0 * D) + tid);
        z0 += w0;
        float2 f0 = __half22float2(hv0);
        ax0 = fmaf(w0, f0.x, ax0); ay0 = fmaf(w0, f0.y, ay0);
    }
    float inv = 1.f / (z0 + z1);
    float ox = (ax0 + ax1) * inv + bias[2 * tid];
    float oy = (ay0 + ay1) * inv + bias[2 * tid + 1];
    if (MODE == 1) {
        ox = fmaxf(ox, 0.f);
        oy = fmaxf(oy, 0.f);
        ((__half2*)outp)[(size_t)node * (D / 2) + tid] = __floats2half2_rn(ox, oy);
    } else {
        ((float2*)outp)[(size_t)node * (D / 2) + tid] = make_float2(ox, oy);
    }
}

// ---------------- launch ----------------
extern "C" void kernel_launch(void* const* d_in, const int* in_sizes, int n_in,
                              void* d_out, int out_size) {
    const float* x   = (const float*)d_in[0];
    const int*   ei  = (const int*)  d_in[1];
    const float* W1  = (const float*)d_in[2];
    const float* as1 = (const float*)d_in[3];
    const float* ad1 = (const float*)d_in[4];
    const float* b1  = (const float*)d_in[5];
    const float* W2  = (const float*)d_in[6];
    const float* as2 = (const float*)d_in[7];
    const float* ad2 = (const float*)d_in[8];
    const float* b2  = (const float*)d_in[9];
    float* out = (float*)d_out;

    const int n     = in_sizes[0] / D;
    const int e_raw = in_sizes[1] / 2;
    const int e_tot = e_raw + n;

    float *es1, *ed1, *es2, *ed2;
    __half *h1, *h2, *xh, *gh, *w1h, *w2h;
    cudaGetSymbolAddress((void**)&h1,  g_h1);
    cudaGetSymbolAddress((void**)&h2,  g_h2);
    cudaGetSymbolAddress((void**)&es1, g_es1);
    cudaGetSymbolAddress((void**)&ed1, g_ed1);
    cudaGetSymbolAddress((void**)&es2, g_es2);
    cudaGetSymbolAddress((void**)&ed2, g_ed2);
    cudaGetSymbolAddress((void**)&xh,  g_xh);
    cudaGetSymbolAddress((void**)&gh,  g_gh);
    cudaGetSymbolAddress((void**)&w1h, g_w1h);
    cudaGetSymbolAddress((void**)&w2h, g_w2h);

    cudaFuncSetAttribute(gemm_mma_kernel, cudaFuncAttributeMaxDynamicSharedMemorySize, GEMM_SMEM);

    static cudaStream_t s_csr = nullptr;
    static cudaEvent_t  e_fork = nullptr, e_csr = nullptr;
    if (!s_csr) {
        if (cudaStreamCreateWithFlags(&s_csr, cudaStreamNonBlocking) != cudaSuccess)
            s_csr = nullptr;
        cudaEventCreateWithFlags(&e_fork, cudaEventDisableTiming);
        cudaEventCreateWithFlags(&e_csr, cudaEventDisableTiming);
    }
    cudaStream_t cs = s_csr ? s_csr : (cudaStream_t)0;

    if (s_csr) {
        cudaEventRecord(e_fork, 0);
        cudaStreamWaitEvent(cs, e_fork, 0);
    }

    // --- side stream: CSR chain + W2 transpose ---
    dim3 tgrid(D / 32, D / 32);
    zero_kernel<<<(n + 255) / 256, 256, 0, cs>>>(n);
    hist_kernel<<<(e_tot + 255) / 256, 256, 0, cs>>>(ei, e_raw, n);
    scan_kernel<<<1, 1024, 0, cs>>>(n);
    scatter_kernel<<<(e_tot + 255) / 256, 256, 0, cs>>>(ei, e_raw, n);
    transpose_kernel<<<tgrid, dim3(32, 8), 0, cs>>>(W2, w2h);
    if (s_csr) cudaEventRecord(e_csr, cs);

    // --- main stream: x split + W1 transpose ---
    split_kernel<<<(n * D / 4 + 255) / 256, 256>>>(x, xh, n * D / 4);
    transpose_kernel<<<tgrid, dim3(32, 8)>>>(W1, w1h);

    // join before gemm1 (epilogue atomics need zeroed es1/ed1)
    if (s_csr) cudaStreamWaitEvent((cudaStream_t)0, e_csr, 0);

    dim3 gemm_grid(D / 128, (n + 127) / 128);

    // --- layer 1 ---
    gemm_mma_kernel<<<gemm_grid, 512, GEMM_SMEM>>>(xh, w1h, h1, as1, ad1, es1, ed1, n);
    wcalc_kernel<<<(e_tot + 255) / 256, 256>>>(es1, ed1, e_tot);
    agg_kernel<1><<<n, 384>>>(h1, b1, gh);

    // --- layer 2 ---
    gemm_mma_kernel<<<gemm_grid, 512, GEMM_SMEM>>>(gh, w2h, h2, as2, ad2, es2, ed2, n);
    wcalc_kernel<<<(e_tot + 255) / 256, 256>>>(es2, ed2, e_tot);
    agg_kernel<0><<<n, 384>>>(h2, b2, out);
}

// round 9
// speedup vs baseline: 1.1628x; 1.1628x over previous
#include <cuda_runtime.h>
#include <cuda_fp16.h>
#include <cstdint>
#include <math.h>

#define D 768
#define N_MAX 10000
#define E_RAW_MAX 100000
#define E_TOT_MAX (E_RAW_MAX + N_MAX)

// ---------------- scratch (device globals; no allocation allowed) ----------------
__device__ __half g_h1[(size_t)N_MAX * D];
__device__ __half g_h2[(size_t)N_MAX * D];
__device__ __half g_xh[(size_t)N_MAX * D];
__device__ __half g_gh[(size_t)N_MAX * D];
__device__ __half g_w1h[D * D];
__device__ __half g_w2h[D * D];
__device__ float g_es1[N_MAX], g_ed1[N_MAX];
__device__ float g_es2[N_MAX], g_ed2[N_MAX];
__device__ int   g_off[N_MAX + 1];
__device__ int   g_cur[N_MAX];
__device__ int   g_csr_src[E_TOT_MAX];
__device__ int   g_csr_dst[E_TOT_MAX];
__device__ float g_wbuf[E_TOT_MAX];

// ================= helpers =================
__device__ __forceinline__ uint32_t smem_u32(const void* p) {
    uint32_t a;
    asm("{ .reg .u64 t; cvta.to.shared.u64 t, %1; cvt.u32.u64 %0, t; }" : "=r"(a) : "l"(p));
    return a;
}
__device__ __forceinline__ uint32_t sw128(uint32_t x) { return x ^ ((x >> 3) & 0x70); }

__device__ __forceinline__ void cp_async16(uint32_t dst, const void* src) {
    asm volatile("cp.async.cg.shared.global [%0], [%1], 16;" :: "r"(dst), "l"(src) : "memory");
}
__device__ __forceinline__ void ldsm4(uint32_t* r, uint32_t addr) {
    asm volatile("ldmatrix.sync.aligned.m8n8.x4.shared.b16 {%0,%1,%2,%3}, [%4];"
                 : "=r"(r[0]), "=r"(r[1]), "=r"(r[2]), "=r"(r[3]) : "r"(addr));
}
__device__ __forceinline__ void mma_fp16(float* c, const uint32_t* a, const uint32_t* b) {
    asm volatile("mma.sync.aligned.m16n8k16.row.col.f32.f16.f16.f32 "
                 "{%0,%1,%2,%3}, {%4,%5,%6,%7}, {%8,%9}, {%0,%1,%2,%3};"
                 : "+f"(c[0]), "+f"(c[1]), "+f"(c[2]), "+f"(c[3])
                 : "r"(a[0]), "r"(a[1]), "r"(a[2]), "r"(a[3]), "r"(b[0]), "r"(b[1]));
}

// ---------------- zero: cursors + dot accumulators ----------------
__global__ void zero_kernel(int n) {
    int i = blockIdx.x * blockDim.x + threadIdx.x;
    if (i < n) {
        g_cur[i] = 0;
        g_es1[i] = 0.f; g_ed1[i] = 0.f;
        g_es2[i] = 0.f; g_ed2[i] = 0.f;
    }
}
__global__ void hist_kernel(const int* __restrict__ ei, int e_raw, int n) {
    int e = blockIdx.x * blockDim.x + threadIdx.x;
    int e_tot = e_raw + n;
    if (e >= e_tot) return;
    int dst = (e < e_raw) ? ei[e_raw + e] : (e - e_raw);
    atomicAdd(&g_cur[dst], 1);
}
__global__ void scan_kernel(int n) {
    __shared__ int sh[1024];
    __shared__ int s_carry;
    int tid = threadIdx.x;
    if (tid == 0) s_carry = 0;
    __syncthreads();
    for (int base = 0; base < n; base += 1024) {
        int i = base + tid;
        int v = (i < n) ? g_cur[i] : 0;
        sh[tid] = v;
        __syncthreads();
        for (int off = 1; off < 1024; off <<= 1) {
            int t = (tid >= off) ? sh[tid - off] : 0;
            __syncthreads();
            sh[tid] += t;
            __syncthreads();
        }
        int excl = sh[tid] - v;
        int carry = s_carry;
        if (i < n) { g_off[i] = carry + excl; g_cur[i] = carry + excl; }
        __syncthreads();
        if (tid == 1023) s_carry = carry + sh[1023];
        __syncthreads();
    }
    if (tid == 0) g_off[n] = s_carry;
}
__global__ void scatter_kernel(const int* __restrict__ ei, int e_raw, int n) {
    int e = blockIdx.x * blockDim.x + threadIdx.x;
    int e_tot = e_raw + n;
    if (e >= e_tot) return;
    int src = (e < e_raw) ? ei[e]         : (e - e_raw);
    int dst = (e < e_raw) ? ei[e_raw + e] : (e - e_raw);
    int pos = atomicAdd(&g_cur[dst], 1);
    g_csr_src[pos] = src;
    g_csr_dst[pos] = dst;
}

// ---------------- per-edge softmax weight ----------------
__global__ void wcalc_kernel(const float* __restrict__ es, const float* __restrict__ ed,
                             int e_tot) {
    int i = blockIdx.x * blockDim.x + threadIdx.x;
    if (i >= e_tot) return;
    float e = __ldg(&es[g_csr_src[i]]) + __ldg(&ed[g_csr_dst[i]]);
    e = (e > 0.f) ? e : 0.2f * e;
    g_wbuf[i] = expf(e);
}

// ---------------- fp32 -> fp16 ----------------
__global__ void split_kernel(const float* __restrict__ x,
                             __half* __restrict__ xh, int total4) {
    int i = blockIdx.x * blockDim.x + threadIdx.x;
    if (i < total4) {
        float4 v = *(const float4*)(x + i * 4);
        __half2* o = (__half2*)(xh + i * 4);
        o[0] = __floats2half2_rn(v.x, v.y);
        o[1] = __floats2half2_rn(v.z, v.w);
    }
}

// ---------------- W[k][n] -> Wt[n][k] fp16 ----------------
__global__ void transpose_kernel(const float* __restrict__ W,
                                 __half* __restrict__ Th) {
    __shared__ float sh[32][33];
    int n0 = blockIdx.x * 32, k0 = blockIdx.y * 32;
    int tx = threadIdx.x, ty = threadIdx.y;
#pragma unroll
    for (int j = 0; j < 32; j += 8)
        sh[ty + j][tx] = W[(size_t)(k0 + ty + j) * D + n0 + tx];
    __syncthreads();
#pragma unroll
    for (int j = 0; j < 32; j += 8)
        Th[(size_t)(n0 + ty + j) * D + k0 + tx] = __float2half(sh[tx][ty + j]);
}

// ---------------- tensor-core GEMM (fp16, 8 warps, 2 CTA/SM) + fused dots --------
// CTA tile 128x128, warp tile 64x32 (2M x 4N), K-chunk 64, 2-stage cp.async.
// SMEM: 2 stages x 32KB = 64KB -> 2 CTAs/SM (128KB), 4 warps/SMSP latency hiding.
#define STAGE_BYTES 32768
#define GEMM_SMEM (2 * STAGE_BYTES)

__global__ __launch_bounds__(256, 2)
void gemm_mma_kernel(const __half* __restrict__ Ah,
                     const __half* __restrict__ Bh,
                     __half* __restrict__ C,
                     const float* __restrict__ a_src,
                     const float* __restrict__ a_dst,
                     float* __restrict__ es, float* __restrict__ ed,
                     int M) {
    extern __shared__ __align__(1024) char smem[];
    const uint32_t sb = smem_u32(smem);
    const int tid  = threadIdx.x;
    const int wid  = tid >> 5;
    const int lane = tid & 31;
    const int m0 = blockIdx.y * 128;
    const int n0 = blockIdx.x * 128;
    const int warp_m = (wid & 1) * 64;
    const int warp_n = (wid >> 1) * 32;

    float acc[4][4][4];
#pragma unroll
    for (int i = 0; i < 4; i++)
#pragma unroll
        for (int j = 0; j < 4; j++)
#pragma unroll
            for (int k = 0; k < 4; k++) acc[i][j][k] = 0.f;

    auto issue_chunk = [&](int c) {
        const uint32_t st = sb + (uint32_t)(c & 1) * STAGE_BYTES;
        const int kc0 = c * 64;
#pragma unroll
        for (int i = 0; i < 4; i++) {
            int idx = i * 256 + tid;
            int row = idx >> 3, cc = idx & 7;
            uint32_t so = sw128((uint32_t)(row * 128 + cc * 16));
            int m = m0 + row; if (m >= M) m = M - 1;   // clamp: rows >= M never stored
            cp_async16(st + 0     + so, Ah + (size_t)m * D + kc0 + cc * 8);
            cp_async16(st + 16384 + so, Bh + (size_t)(n0 + row) * D + kc0 + cc * 8);
        }
    };

    issue_chunk(0);
    asm volatile("cp.async.commit_group;" ::: "memory");

#pragma unroll 1
    for (int c = 0; c < 12; c++) {
        if (c + 1 < 12) {
            issue_chunk(c + 1);
            asm volatile("cp.async.commit_group;" ::: "memory");
            asm volatile("cp.async.wait_group 1;" ::: "memory");
        } else {
            asm volatile("cp.async.wait_group 0;" ::: "memory");
        }
        __syncthreads();

        const uint32_t st = sb + (uint32_t)(c & 1) * STAGE_BYTES;
#pragma unroll
        for (int ks = 0; ks < 4; ks++) {
            uint32_t af[4][4], bf[2][4];
            const int arow = lane & 15;
            const int acol = (ks * 16 + (lane >> 4) * 8) * 2;
#pragma unroll
            for (int mt = 0; mt < 4; mt++) {
                uint32_t off = sw128((uint32_t)((warp_m + mt * 16 + arow) * 128 + acol));
                ldsm4(af[mt], st + off);
            }
            const int brow = (lane & 7) + ((lane >> 4) << 3);
            const int bcol = (ks * 16 + ((lane >> 3) & 1) * 8) * 2;
#pragma unroll
            for (int p = 0; p < 2; p++) {
                uint32_t off = sw128((uint32_t)((warp_n + p * 16 + brow) * 128 + bcol));
                ldsm4(bf[p], st + 16384 + off);
            }
#pragma unroll
            for (int mt = 0; mt < 4; mt++) {
#pragma unroll
                for (int nt = 0; nt < 4; nt++)
                    mma_fp16(acc[mt][nt], af[mt], &bf[nt >> 1][(nt & 1) * 2]);
            }
        }
        __syncthreads();
    }

    // epilogue: store C (fp16) + fused dot partials
    const int er = lane >> 2;
    const int ec = (lane & 3) * 2;
#pragma unroll
    for (int mt = 0; mt < 4; mt++) {
        int row = m0 + warp_m + mt * 16 + er;
        float s0 = 0.f, d0 = 0.f, s1 = 0.f, d1 = 0.f;
#pragma unroll
        for (int nt = 0; nt < 4; nt++) {
            int col = n0 + warp_n + nt * 8 + ec;
            if (row < M)
                *(__half2*)(C + (size_t)row * D + col) =
                    __floats2half2_rn(acc[mt][nt][0], acc[mt][nt][1]);
            if (row + 8 < M)
                *(__half2*)(C + (size_t)(row + 8) * D + col) =
                    __floats2half2_rn(acc[mt][nt][2], acc[mt][nt][3]);
            float as0 = __ldg(a_src + col), as1 = __ldg(a_src + col + 1);
            float ad0 = __ldg(a_dst + col), ad1 = __ldg(a_dst + col + 1);
            s0 = fmaf(acc[mt][nt][0], as0, fmaf(acc[mt][nt][1], as1, s0));
            d0 = fmaf(acc[mt][nt][0], ad0, fmaf(acc[mt][nt][1], ad1, d0));
            s1 = fmaf(acc[mt][nt][2], as0, fmaf(acc[mt][nt][3], as1, s1));
            d1 = fmaf(acc[mt][nt][2], ad0, fmaf(acc[mt][nt][3], ad1, d1));
        }
#pragma unroll
        for (int o = 1; o < 4; o <<= 1) {
            s0 += __shfl_xor_sync(0xffffffffu, s0, o);
            d0 += __shfl_xor_sync(0xffffffffu, d0, o);
            s1 += __shfl_xor_sync(0xffffffffu, s1, o);
            d1 += __shfl_xor_sync(0xffffffffu, d1, o);
        }
        if ((lane & 3) == 0) {
            if (row < M)     { atomicAdd(&es[row],     s0); atomicAdd(&ed[row],     d0); }
            if (row + 8 < M) { atomicAdd(&es[row + 8], s1); atomicAdd(&ed[row + 8], d1); }
        }
    }
}

// ---------------- segment aggregation (weights precomputed, x2 unrolled) ------------
template <int MODE>
__global__ __launch_bounds__(384)
void agg_kernel(const __half* __restrict__ h, const float* __restrict__ bias,
                void* __restrict__ outp) {
    const int node = blockIdx.x;
    const int tid = threadIdx.x;
    const int beg = g_off[node];
    const int end = g_off[node + 1];

    float z0 = 0.f, z1 = 0.f;
    float ax0 = 0.f, ay0 = 0.f, ax1 = 0.f, ay1 = 0.f;
    int i = beg;
    for (; i + 1 < end; i += 2) {
        float w0 = __ldg(&g_wbuf[i]);
        float w1 = __ldg(&g_wbuf[i + 1]);
        int s0 = __ldg(&g_csr_src[i]);
        int s1 = __ldg(&g_csr_src[i + 1]);
        __half2 hv0 = __ldg((const __half2*)(h + (size_t)s0 * D) + tid);
        __half2 hv1 = __ldg((const __half2*)(h + (size_t)s1 * D) + tid);
        z0 += w0; z1 += w1;
        float2 f0 = __half22float2(hv0);
        float2 f1 = __half22float2(hv1);
        ax0 = fmaf(w0, f0.x, ax0); ay0 = fmaf(w0, f0.y, ay0);
        ax1 = fmaf(w1, f1.x, ax1); ay1 = fmaf(w1, f1.y, ay1);
    }
    if (i < end) {
        float w0 = __ldg(&g_wbuf[i]);
        int s0 = __ldg(&g_csr_src[i]);
        __half2 hv0 = __ldg((const __half2*)(h + (size_t)s0 * D) + tid);
        z0 += w0;
        float2 f0 = __half22float2(hv0);
        ax0 = fmaf(w0, f0.x, ax0); ay0 = fmaf(w0, f0.y, ay0);
    }
    float inv = 1.f / (z0 + z1);
    float ox = (ax0 + ax1) * inv + bias[2 * tid];
    float oy = (ay0 + ay1) * inv + bias[2 * tid + 1];
    if (MODE == 1) {
        ox = fmaxf(ox, 0.f);
        oy = fmaxf(oy, 0.f);
        ((__half2*)outp)[(size_t)node * (D / 2) + tid] = __floats2half2_rn(ox, oy);
    } else {
        ((float2*)outp)[(size_t)node * (D / 2) + tid] = make_float2(ox, oy);
    }
}

// ---------------- launch ----------------
extern "C" void kernel_launch(void* const* d_in, const int* in_sizes, int n_in,
                              void* d_out, int out_size) {
    const float* x   = (const float*)d_in[0];
    const int*   ei  = (const int*)  d_in[1];
    const float* W1  = (const float*)d_in[2];
    const float* as1 = (const float*)d_in[3];
    const float* ad1 = (const float*)d_in[4];
    const float* b1  = (const float*)d_in[5];
    const float* W2  = (const float*)d_in[6];
    const float* as2 = (const float*)d_in[7];
    const float* ad2 = (const float*)d_in[8];
    const float* b2  = (const float*)d_in[9];
    float* out = (float*)d_out;

    const int n     = in_sizes[0] / D;
    const int e_raw = in_sizes[1] / 2;
    const int e_tot = e_raw + n;

    float *es1, *ed1, *es2, *ed2;
    __half *h1, *h2, *xh, *gh, *w1h, *w2h;
    cudaGetSymbolAddress((void**)&h1,  g_h1);
    cudaGetSymbolAddress((void**)&h2,  g_h2);
    cudaGetSymbolAddress((void**)&es1, g_es1);
    cudaGetSymbolAddress((void**)&ed1, g_ed1);
    cudaGetSymbolAddress((void**)&es2, g_es2);
    cudaGetSymbolAddress((void**)&ed2, g_ed2);
    cudaGetSymbolAddress((void**)&xh,  g_xh);
    cudaGetSymbolAddress((void**)&gh,  g_gh);
    cudaGetSymbolAddress((void**)&w1h, g_w1h);
    cudaGetSymbolAddress((void**)&w2h, g_w2h);

    cudaFuncSetAttribute(gemm_mma_kernel, cudaFuncAttributeMaxDynamicSharedMemorySize, GEMM_SMEM);

    static cudaStream_t s_csr = nullptr;
    static cudaEvent_t  e_fork = nullptr, e_csr = nullptr;
    if (!s_csr) {
        if (cudaStreamCreateWithFlags(&s_csr, cudaStreamNonBlocking) != cudaSuccess)
            s_csr = nullptr;
        cudaEventCreateWithFlags(&e_fork, cudaEventDisableTiming);
        cudaEventCreateWithFlags(&e_csr, cudaEventDisableTiming);
    }
    cudaStream_t cs = s_csr ? s_csr : (cudaStream_t)0;

    if (s_csr) {
        cudaEventRecord(e_fork, 0);
        cudaStreamWaitEvent(cs, e_fork, 0);
    }

    // --- side stream: CSR chain + W2 transpose ---
    dim3 tgrid(D / 32, D / 32);
    zero_kernel<<<(n + 255) / 256, 256, 0, cs>>>(n);
    hist_kernel<<<(e_tot + 255) / 256, 256, 0, cs>>>(ei, e_raw, n);
    scan_kernel<<<1, 1024, 0, cs>>>(n);
    scatter_kernel<<<(e_tot + 255) / 256, 256, 0, cs>>>(ei, e_raw, n);
    transpose_kernel<<<tgrid, dim3(32, 8), 0, cs>>>(W2, w2h);
    if (s_csr) cudaEventRecord(e_csr, cs);

    // --- main stream: x split + W1 transpose ---
    split_kernel<<<(n * D / 4 + 255) / 256, 256>>>(x, xh, n * D / 4);
    transpose_kernel<<<tgrid, dim3(32, 8)>>>(W1, w1h);

    // join before gemm1 (epilogue atomics need zeroed es1/ed1)
    if (s_csr) cudaStreamWaitEvent((cudaStream_t)0, e_csr, 0);

    dim3 gemm_grid(D / 128, (n + 127) / 128);

    // --- layer 1 ---
    gemm_mma_kernel<<<gemm_grid, 256, GEMM_SMEM>>>(xh, w1h, h1, as1, ad1, es1, ed1, n);
    wcalc_kernel<<<(e_tot + 255) / 256, 256>>>(es1, ed1, e_tot);
    agg_kernel<1><<<n, 384>>>(h1, b1, gh);

    // --- layer 2 ---
    gemm_mma_kernel<<<gemm_grid, 256, GEMM_SMEM>>>(gh, w2h, h2, as2, ad2, es2, ed2, n);
    wcalc_kernel<<<(e_tot + 255) / 256, 256>>>(es2, ed2, e_tot);
    agg_kernel<0><<<n, 384>>>(h2, b2, out);
}

// round 11
// speedup vs baseline: 1.2331x; 1.0604x over previous
#include <cuda_runtime.h>
#include <cuda_fp16.h>
#include <cstdint>
#include <math.h>

#define D 768
#define N_MAX 10000
#define E_RAW_MAX 100000
#define E_TOT_MAX (E_RAW_MAX + N_MAX)

// ---------------- scratch (device globals; no allocation allowed) ----------------
__device__ __half g_h1[(size_t)N_MAX * D];
__device__ __half g_h2[(size_t)N_MAX * D];
__device__ __half g_xh[(size_t)N_MAX * D];
__device__ __half g_gh[(size_t)N_MAX * D];
__device__ __half g_w1h[D * D];
__device__ __half g_w2h[D * D];
__device__ float g_es1[N_MAX], g_ed1[N_MAX];
__device__ float g_es2[N_MAX], g_ed2[N_MAX];
__device__ float g_v1s[D], g_v1d[D];   // W1 @ a_src1, W1 @ a_dst1  (v[k] = sum_n W[k,n] a[n])
__device__ float g_v2s[D], g_v2d[D];   // W2 @ a_src2, W2 @ a_dst2
__device__ int   g_off[N_MAX + 1];
__device__ int   g_cur[N_MAX];
__device__ int   g_csr_src[E_TOT_MAX];

// ================= helpers =================
__device__ __forceinline__ uint32_t smem_u32(const void* p) {
    uint32_t a;
    asm("{ .reg .u64 t; cvta.to.shared.u64 t, %1; cvt.u32.u64 %0, t; }" : "=r"(a) : "l"(p));
    return a;
}
__device__ __forceinline__ uint32_t sw128(uint32_t x) { return x ^ ((x >> 3) & 0x70); }

__device__ __forceinline__ void cp_async16(uint32_t dst, const void* src) {
    asm volatile("cp.async.cg.shared.global [%0], [%1], 16;" :: "r"(dst), "l"(src) : "memory");
}
__device__ __forceinline__ void ldsm4(uint32_t* r, uint32_t addr) {
    asm volatile("ldmatrix.sync.aligned.m8n8.x4.shared.b16 {%0,%1,%2,%3}, [%4];"
                 : "=r"(r[0]), "=r"(r[1]), "=r"(r[2]), "=r"(r[3]) : "r"(addr));
}
__device__ __forceinline__ void mma_fp16(float* c, const uint32_t* a, const uint32_t* b) {
    asm volatile("mma.sync.aligned.m16n8k16.row.col.f32.f16.f16.f32 "
                 "{%0,%1,%2,%3}, {%4,%5,%6,%7}, {%8,%9}, {%0,%1,%2,%3};"
                 : "+f"(c[0]), "+f"(c[1]), "+f"(c[2]), "+f"(c[3])
                 : "r"(a[0]), "r"(a[1]), "r"(a[2]), "r"(a[3]), "r"(b[0]), "r"(b[1]));
}

// ---------------- CSR build ----------------
__global__ void zero_kernel(int n) {
    int i = blockIdx.x * blockDim.x + threadIdx.x;
    if (i < n) g_cur[i] = 0;
}
__global__ void hist_kernel(const int* __restrict__ ei, int e_raw, int n) {
    int e = blockIdx.x * blockDim.x + threadIdx.x;
    int e_tot = e_raw + n;
    if (e >= e_tot) return;
    int dst = (e < e_raw) ? ei[e_raw + e] : (e - e_raw);
    atomicAdd(&g_cur[dst], 1);
}
__global__ void scan_kernel(int n) {
    __shared__ int sh[1024];
    __shared__ int s_carry;
    int tid = threadIdx.x;
    if (tid == 0) s_carry = 0;
    __syncthreads();
    for (int base = 0; base < n; base += 1024) {
        int i = base + tid;
        int v = (i < n) ? g_cur[i] : 0;
        sh[tid] = v;
        __syncthreads();
        for (int off = 1; off < 1024; off <<= 1) {
            int t = (tid >= off) ? sh[tid - off] : 0;
            __syncthreads();
            sh[tid] += t;
            __syncthreads();
        }
        int excl = sh[tid] - v;
        int carry = s_carry;
        if (i < n) { g_off[i] = carry + excl; g_cur[i] = carry + excl; }
        __syncthreads();
        if (tid == 1023) s_carry = carry + sh[1023];
        __syncthreads();
    }
    if (tid == 0) g_off[n] = s_carry;
}
__global__ void scatter_kernel(const int* __restrict__ ei, int e_raw, int n) {
    int e = blockIdx.x * blockDim.x + threadIdx.x;
    int e_tot = e_raw + n;
    if (e >= e_tot) return;
    int src = (e < e_raw) ? ei[e]         : (e - e_raw);
    int dst = (e < e_raw) ? ei[e_raw + e] : (e - e_raw);
    int pos = atomicAdd(&g_cur[dst], 1);
    g_csr_src[pos] = src;
}

// ---------------- v = W @ a : v[k] = sum_n W[k][n] * a[n]  (warp per row k) --------
__global__ void vcalc_kernel(const float* __restrict__ W,
                             const float* __restrict__ asr, const float* __restrict__ adt,
                             float* __restrict__ vs, float* __restrict__ vd) {
    int row = (blockIdx.x * blockDim.x + threadIdx.x) >> 5;
    int lane = threadIdx.x & 31;
    if (row >= D) return;
    const float4* wr = (const float4*)(W + (size_t)row * D);
    float s = 0.f, d = 0.f;
#pragma unroll
    for (int i = lane; i < D / 4; i += 32) {
        float4 w = __ldg(wr + i);
        float4 a = *(const float4*)(asr + i * 4);
        float4 b = *(const float4*)(adt + i * 4);
        s = fmaf(w.x, a.x, fmaf(w.y, a.y, fmaf(w.z, a.z, fmaf(w.w, a.w, s))));
        d = fmaf(w.x, b.x, fmaf(w.y, b.y, fmaf(w.z, b.z, fmaf(w.w, b.w, d))));
    }
#pragma unroll
    for (int o = 16; o; o >>= 1) {
        s += __shfl_down_sync(0xffffffffu, s, o);
        d += __shfl_down_sync(0xffffffffu, d, o);
    }
    if (lane == 0) { vs[row] = s; vd[row] = d; }
}

// ---------------- es/ed = x @ v (warp per row) ----------------
__global__ void rowdot_kernel(const float* __restrict__ x,
                              const float* __restrict__ vs, const float* __restrict__ vd,
                              float* __restrict__ es, float* __restrict__ ed, int n) {
    int warp = (blockIdx.x * blockDim.x + threadIdx.x) >> 5;
    int lane = threadIdx.x & 31;
    if (warp >= n) return;
    const float4* row = (const float4*)(x + (size_t)warp * D);
    float s = 0.f, d = 0.f;
#pragma unroll
    for (int i = lane; i < D / 4; i += 32) {
        float4 v = __ldg(row + i);
        float4 a = *(const float4*)(vs + i * 4);
        float4 b = *(const float4*)(vd + i * 4);
        s = fmaf(v.x, a.x, fmaf(v.y, a.y, fmaf(v.z, a.z, fmaf(v.w, a.w, s))));
        d = fmaf(v.x, b.x, fmaf(v.y, b.y, fmaf(v.z, b.z, fmaf(v.w, b.w, d))));
    }
#pragma unroll
    for (int o = 16; o; o >>= 1) {
        s += __shfl_down_sync(0xffffffffu, s, o);
        d += __shfl_down_sync(0xffffffffu, d, o);
    }
    if (lane == 0) { es[warp] = s; ed[warp] = d; }
}

// ---------------- fp32 -> fp16 ----------------
__global__ void split_kernel(const float* __restrict__ x,
                             __half* __restrict__ xh, int total4) {
    int i = blockIdx.x * blockDim.x + threadIdx.x;
    if (i < total4) {
        float4 v = *(const float4*)(x + i * 4);
        __half2* o = (__half2*)(xh + i * 4);
        o[0] = __floats2half2_rn(v.x, v.y);
        o[1] = __floats2half2_rn(v.z, v.w);
    }
}

// ---------------- W[k][n] -> Wt[n][k] fp16 ----------------
__global__ void transpose_kernel(const float* __restrict__ W,
                                 __half* __restrict__ Th) {
    __shared__ float sh[32][33];
    int n0 = blockIdx.x * 32, k0 = blockIdx.y * 32;
    int tx = threadIdx.x, ty = threadIdx.y;
#pragma unroll
    for (int j = 0; j < 32; j += 8)
        sh[ty + j][tx] = W[(size_t)(k0 + ty + j) * D + n0 + tx];
    __syncthreads();
#pragma unroll
    for (int j = 0; j < 32; j += 8)
        Th[(size_t)(n0 + ty + j) * D + k0 + tx] = __float2half(sh[tx][ty + j]);
}

// ---------------- tensor-core GEMM (fp16, 8 warps, 2 CTA/SM) ----------------
#define STAGE_BYTES 32768
#define GEMM_SMEM (2 * STAGE_BYTES)

__global__ __launch_bounds__(256, 2)
void gemm_mma_kernel(const __half* __restrict__ Ah,
                     const __half* __restrict__ Bh,
                     __half* __restrict__ C, int M) {
    extern __shared__ __align__(1024) char smem[];
    const uint32_t sb = smem_u32(smem);
    const int tid  = threadIdx.x;
    const int wid  = tid >> 5;
    const int lane = tid & 31;
    const int m0 = blockIdx.y * 128;
    const int n0 = blockIdx.x * 128;
    const int warp_m = (wid & 1) * 64;
    const int warp_n = (wid >> 1) * 32;

    float acc[4][4][4];
#pragma unroll
    for (int i = 0; i < 4; i++)
#pragma unroll
        for (int j = 0; j < 4; j++)
#pragma unroll
            for (int k = 0; k < 4; k++) acc[i][j][k] = 0.f;

    auto issue_chunk = [&](int c) {
        const uint32_t st = sb + (uint32_t)(c & 1) * STAGE_BYTES;
        const int kc0 = c * 64;
#pragma unroll
        for (int i = 0; i < 4; i++) {
            int idx = i * 256 + tid;
            int row = idx >> 3, cc = idx & 7;
            uint32_t so = sw128((uint32_t)(row * 128 + cc * 16));
            int m = m0 + row; if (m >= M) m = M - 1;   // clamp: rows >= M never stored
            cp_async16(st + 0     + so, Ah + (size_t)m * D + kc0 + cc * 8);
            cp_async16(st + 16384 + so, Bh + (size_t)(n0 + row) * D + kc0 + cc * 8);
        }
    };

    issue_chunk(0);
    asm volatile("cp.async.commit_group;" ::: "memory");

#pragma unroll 1
    for (int c = 0; c < 12; c++) {
        if (c + 1 < 12) {
            issue_chunk(c + 1);
            asm volatile("cp.async.commit_group;" ::: "memory");
            asm volatile("cp.async.wait_group 1;" ::: "memory");
        } else {
            asm volatile("cp.async.wait_group 0;" ::: "memory");
        }
        __syncthreads();

        const uint32_t st = sb + (uint32_t)(c & 1) * STAGE_BYTES;
#pragma unroll
        for (int ks = 0; ks < 4; ks++) {
            uint32_t af[4][4], bf[2][4];
            const int arow = lane & 15;
            const int acol = (ks * 16 + (lane >> 4) * 8) * 2;
#pragma unroll
            for (int mt = 0; mt < 4; mt++) {
                uint32_t off = sw128((uint32_t)((warp_m + mt * 16 + arow) * 128 + acol));
                ldsm4(af[mt], st + off);
            }
            const int brow = (lane & 7) + ((lane >> 4) << 3);
            const int bcol = (ks * 16 + ((lane >> 3) & 1) * 8) * 2;
#pragma unroll
            for (int p = 0; p < 2; p++) {
                uint32_t off = sw128((uint32_t)((warp_n + p * 16 + brow) * 128 + bcol));
                ldsm4(bf[p], st + 16384 + off);
            }
#pragma unroll
            for (int mt = 0; mt < 4; mt++) {
#pragma unroll
                for (int nt = 0; nt < 4; nt++)
                    mma_fp16(acc[mt][nt], af[mt], &bf[nt >> 1][(nt & 1) * 2]);
            }
        }
        __syncthreads();
    }

    const int er = lane >> 2;
    const int ec = (lane & 3) * 2;
#pragma unroll
    for (int mt = 0; mt < 4; mt++) {
        int row = m0 + warp_m + mt * 16 + er;
#pragma unroll
        for (int nt = 0; nt < 4; nt++) {
            int col = n0 + warp_n + nt * 8 + ec;
            if (row < M)
                *(__half2*)(C + (size_t)row * D + col) =
                    __floats2half2_rn(acc[mt][nt][0], acc[mt][nt][1]);
            if (row + 8 < M)
                *(__half2*)(C + (size_t)(row + 8) * D + col) =
                    __floats2half2_rn(acc[mt][nt][2], acc[mt][nt][3]);
        }
    }
}

// ---------------- segment softmax + aggregation (inline edge weights) ------------
// 384 threads; thread t owns dims 2t,2t+1. Edge weights computed inline into smem.
// MODE 0: fp32 out + bias. MODE 1: relu -> fp16 out + es2/ed2 = g.v2s / g.v2d
template <int MODE>
__global__ __launch_bounds__(384)
void agg_kernel(const __half* __restrict__ h, const float* __restrict__ bias,
                const float* __restrict__ es, const float* __restrict__ ed,
                const float* __restrict__ v2s, const float* __restrict__ v2d,
                float* __restrict__ es2, float* __restrict__ ed2,
                void* __restrict__ outp) {
    const int node = blockIdx.x;
    const int tid = threadIdx.x;
    const int beg = g_off[node];
    const int end = g_off[node + 1];
    const float edv = ed[node];

    __shared__ float sw[384];
    __shared__ int ssrc[384];

    float z = 0.f, ax = 0.f, ay = 0.f;
    for (int base = beg; base < end; base += 384) {
        int cnt = min(384, end - base);
        if (tid < cnt) {
            int s = __ldg(&g_csr_src[base + tid]);
            ssrc[tid] = s;
            float e = __ldg(&es[s]) + edv;
            e = (e > 0.f) ? e : 0.2f * e;
            sw[tid] = expf(e);
        }
        __syncthreads();
        for (int j = 0; j < cnt; j++) {
            float w = sw[j];
            z += w;
            __half2 hv = __ldg((const __half2*)(h + (size_t)ssrc[j] * D) + tid);
            float2 hf = __half22float2(hv);
            ax = fmaf(w, hf.x, ax);
            ay = fmaf(w, hf.y, ay);
        }
        __syncthreads();
    }
    float inv = 1.f / z;
    float ox = ax * inv + bias[2 * tid];
    float oy = ay * inv + bias[2 * tid + 1];
    if (MODE == 1) {
        ox = fmaxf(ox, 0.f);
        oy = fmaxf(oy, 0.f);
        ((__half2*)outp)[(size_t)node * (D / 2) + tid] = __floats2half2_rn(ox, oy);
        // es2/ed2 = g . v2s / g . v2d  (fp32 pre-quantization g)
        float ps = ox * __ldg(&v2s[2 * tid]) + oy * __ldg(&v2s[2 * tid + 1]);
        float pd = ox * __ldg(&v2d[2 * tid]) + oy * __ldg(&v2d[2 * tid + 1]);
#pragma unroll
        for (int o = 16; o; o >>= 1) {
            ps += __shfl_down_sync(0xffffffffu, ps, o);
            pd += __shfl_down_sync(0xffffffffu, pd, o);
        }
        __shared__ float wrs[12], wrd[12];
        int wid = tid >> 5, lane = tid & 31;
        if (lane == 0) { wrs[wid] = ps; wrd[wid] = pd; }
        __syncthreads();
        if (tid == 0) {
            float a = 0.f, b = 0.f;
#pragma unroll
            for (int j = 0; j < 12; j++) { a += wrs[j]; b += wrd[j]; }
            es2[node] = a;
            ed2[node] = b;
        }
    } else {
        ((float2*)outp)[(size_t)node * (D / 2) + tid] = make_float2(ox, oy);
    }
}

// ---------------- launch ----------------
extern "C" void kernel_launch(void* const* d_in, const int* in_sizes, int n_in,
                              void* d_out, int out_size) {
    const float* x   = (const float*)d_in[0];
    const int*   ei  = (const int*)  d_in[1];
    const float* W1  = (const float*)d_in[2];
    const float* as1 = (const float*)d_in[3];
    const float* ad1 = (const float*)d_in[4];
    const float* b1  = (const float*)d_in[5];
    const float* W2  = (const float*)d_in[6];
    const float* as2 = (const float*)d_in[7];
    const float* ad2 = (const float*)d_in[8];
    const float* b2  = (const float*)d_in[9];
    float* out = (float*)d_out;

    const int n     = in_sizes[0] / D;
    const int e_raw = in_sizes[1] / 2;
    const int e_tot = e_raw + n;

    float *es1, *ed1, *es2, *ed2, *v1s, *v1d, *v2s, *v2d;
    __half *h1, *h2, *xh, *gh, *w1h, *w2h;
    cudaGetSymbolAddress((void**)&h1,  g_h1);
    cudaGetSymbolAddress((void**)&h2,  g_h2);
    cudaGetSymbolAddress((void**)&es1, g_es1);
    cudaGetSymbolAddress((void**)&ed1, g_ed1);
    cudaGetSymbolAddress((void**)&es2, g_es2);
    cudaGetSymbolAddress((void**)&ed2, g_ed2);
    cudaGetSymbolAddress((void**)&v1s, g_v1s);
    cudaGetSymbolAddress((void**)&v1d, g_v1d);
    cudaGetSymbolAddress((void**)&v2s, g_v2s);
    cudaGetSymbolAddress((void**)&v2d, g_v2d);
    cudaGetSymbolAddress((void**)&xh,  g_xh);
    cudaGetSymbolAddress((void**)&gh,  g_gh);
    cudaGetSymbolAddress((void**)&w1h, g_w1h);
    cudaGetSymbolAddress((void**)&w2h, g_w2h);

    cudaFuncSetAttribute(gemm_mma_kernel, cudaFuncAttributeMaxDynamicSharedMemorySize, GEMM_SMEM);

    static cudaStream_t s_csr = nullptr;
    static cudaEvent_t  e_fork = nullptr, e_csr = nullptr;
    if (!s_csr) {
        if (cudaStreamCreateWithFlags(&s_csr, cudaStreamNonBlocking) != cudaSuccess)
            s_csr = nullptr;
        cudaEventCreateWithFlags(&e_fork, cudaEventDisableTiming);
        cudaEventCreateWithFlags(&e_csr, cudaEventDisableTiming);
    }
    cudaStream_t cs = s_csr ? s_csr : (cudaStream_t)0;

    if (s_csr) {
        cudaEventRecord(e_fork, 0);
        cudaStreamWaitEvent(cs, e_fork, 0);
    }

    dim3 tgrid(D / 32, D / 32);

    // --- side stream: CSR chain + W2 transpose + logit matvecs ---
    zero_kernel<<<(n + 255) / 256, 256, 0, cs>>>(n);
    hist_kernel<<<(e_tot + 255) / 256, 256, 0, cs>>>(ei, e_raw, n);
    scan_kernel<<<1, 1024, 0, cs>>>(n);
    scatter_kernel<<<(e_tot + 255) / 256, 256, 0, cs>>>(ei, e_raw, n);
    transpose_kernel<<<tgrid, dim3(32, 8), 0, cs>>>(W2, w2h);
    vcalc_kernel<<<D / 8, 256, 0, cs>>>(W1, as1, ad1, v1s, v1d);
    vcalc_kernel<<<D / 8, 256, 0, cs>>>(W2, as2, ad2, v2s, v2d);
    rowdot_kernel<<<(n + 7) / 8, 256, 0, cs>>>(x, v1s, v1d, es1, ed1, n);
    if (s_csr) cudaEventRecord(e_csr, cs);

    // --- main stream: x split + W1 transpose -> GEMM1 ---
    split_kernel<<<(n * D / 4 + 255) / 256, 256>>>(x, xh, n * D / 4);
    transpose_kernel<<<tgrid, dim3(32, 8)>>>(W1, w1h);

    dim3 gemm_grid(D / 128, (n + 127) / 128);
    gemm_mma_kernel<<<gemm_grid, 256, GEMM_SMEM>>>(xh, w1h, h1, n);

    // join: agg1 needs CSR + es1/ed1 + v2 (side stream)
    if (s_csr) cudaStreamWaitEvent((cudaStream_t)0, e_csr, 0);

    // --- layer 1 aggregation (emits gh + layer-2 logits) ---
    agg_kernel<1><<<n, 384>>>(h1, b1, es1, ed1, v2s, v2d, es2, ed2, gh);

    // --- layer 2 ---
    gemm_mma_kernel<<<gemm_grid, 256, GEMM_SMEM>>>(gh, w2h, h2, n);
    agg_kernel<0><<<n, 384>>>(h2, b2, es2, ed2, nullptr, nullptr, nullptr, nullptr, out);
}

// round 12
// speedup vs baseline: 1.2454x; 1.0100x over previous
#include <cuda_runtime.h>
#include <cuda_fp16.h>
#include <cstdint>
#include <math.h>

#define D 768
#define N_MAX 10000
#define E_RAW_MAX 100000
#define E_TOT_MAX (E_RAW_MAX + N_MAX)

// ---------------- scratch (device globals; no allocation allowed) ----------------
__device__ __half g_h1[(size_t)N_MAX * D];
__device__ __half g_h2[(size_t)N_MAX * D];
__device__ __half g_xh[(size_t)N_MAX * D];
__device__ __half g_gh[(size_t)N_MAX * D];
__device__ __half g_w1h[D * D];
__device__ __half g_w2h[D * D];
__device__ float g_es1[N_MAX], g_ed1[N_MAX];
__device__ float g_es2[N_MAX], g_ed2[N_MAX];
__device__ float g_v1s[D], g_v1d[D];   // W1 @ a_src1, W1 @ a_dst1  (v[k] = sum_n W[k,n] a[n])
__device__ float g_v2s[D], g_v2d[D];   // W2 @ a_src2, W2 @ a_dst2
__device__ int   g_off[N_MAX + 1];
__device__ int   g_cur[N_MAX];
__device__ int   g_csr_src[E_TOT_MAX];

// ================= helpers =================
__device__ __forceinline__ uint32_t smem_u32(const void* p) {
    uint32_t a;
    asm("{ .reg .u64 t; cvta.to.shared.u64 t, %1; cvt.u32.u64 %0, t; }" : "=r"(a) : "l"(p));
    return a;
}
__device__ __forceinline__ uint32_t sw128(uint32_t x) { return x ^ ((x >> 3) & 0x70); }

__device__ __forceinline__ void cp_async16(uint32_t dst, const void* src) {
    asm volatile("cp.async.cg.shared.global [%0], [%1], 16;" :: "r"(dst), "l"(src) : "memory");
}
__device__ __forceinline__ void ldsm4(uint32_t* r, uint32_t addr) {
    asm volatile("ldmatrix.sync.aligned.m8n8.x4.shared.b16 {%0,%1,%2,%3}, [%4];"
                 : "=r"(r[0]), "=r"(r[1]), "=r"(r[2]), "=r"(r[3]) : "r"(addr));
}
__device__ __forceinline__ void mma_fp16(float* c, const uint32_t* a, const uint32_t* b) {
    asm volatile("mma.sync.aligned.m16n8k16.row.col.f32.f16.f16.f32 "
                 "{%0,%1,%2,%3}, {%4,%5,%6,%7}, {%8,%9}, {%0,%1,%2,%3};"
                 : "+f"(c[0]), "+f"(c[1]), "+f"(c[2]), "+f"(c[3])
                 : "r"(a[0]), "r"(a[1]), "r"(a[2]), "r"(a[3]), "r"(b[0]), "r"(b[1]));
}

// ---------------- CSR build ----------------
__global__ void zero_kernel(int n) {
    int i = blockIdx.x * blockDim.x + threadIdx.x;
    if (i < n) g_cur[i] = 0;
}
__global__ void hist_kernel(const int* __restrict__ ei, int e_raw, int n) {
    int e = blockIdx.x * blockDim.x + threadIdx.x;
    int e_tot = e_raw + n;
    if (e >= e_tot) return;
    int dst = (e < e_raw) ? ei[e_raw + e] : (e - e_raw);
    atomicAdd(&g_cur[dst], 1);
}
__global__ void scan_kernel(int n) {
    __shared__ int sh[1024];
    __shared__ int s_carry;
    int tid = threadIdx.x;
    if (tid == 0) s_carry = 0;
    __syncthreads();
    for (int base = 0; base < n; base += 1024) {
        int i = base + tid;
        int v = (i < n) ? g_cur[i] : 0;
        sh[tid] = v;
        __syncthreads();
        for (int off = 1; off < 1024; off <<= 1) {
            int t = (tid >= off) ? sh[tid - off] : 0;
            __syncthreads();
            sh[tid] += t;
            __syncthreads();
        }
        int excl = sh[tid] - v;
        int carry = s_carry;
        if (i < n) { g_off[i] = carry + excl; g_cur[i] = carry + excl; }
        __syncthreads();
        if (tid == 1023) s_carry = carry + sh[1023];
        __syncthreads();
    }
    if (tid == 0) g_off[n] = s_carry;
}
__global__ void scatter_kernel(const int* __restrict__ ei, int e_raw, int n) {
    int e = blockIdx.x * blockDim.x + threadIdx.x;
    int e_tot = e_raw + n;
    if (e >= e_tot) return;
    int src = (e < e_raw) ? ei[e]         : (e - e_raw);
    int dst = (e < e_raw) ? ei[e_raw + e] : (e - e_raw);
    int pos = atomicAdd(&g_cur[dst], 1);
    g_csr_src[pos] = src;
}

// ---------------- v = W @ a : v[k] = sum_n W[k][n] * a[n]  (warp per row k) --------
__global__ void vcalc_kernel(const float* __restrict__ W,
                             const float* __restrict__ asr, const float* __restrict__ adt,
                             float* __restrict__ vs, float* __restrict__ vd) {
    int row = (blockIdx.x * blockDim.x + threadIdx.x) >> 5;
    int lane = threadIdx.x & 31;
    if (row >= D) return;
    const float4* wr = (const float4*)(W + (size_t)row * D);
    float s = 0.f, d = 0.f;
#pragma unroll
    for (int i = lane; i < D / 4; i += 32) {
        float4 w = __ldg(wr + i);
        float4 a = *(const float4*)(asr + i * 4);
        float4 b = *(const float4*)(adt + i * 4);
        s = fmaf(w.x, a.x, fmaf(w.y, a.y, fmaf(w.z, a.z, fmaf(w.w, a.w, s))));
        d = fmaf(w.x, b.x, fmaf(w.y, b.y, fmaf(w.z, b.z, fmaf(w.w, b.w, d))));
    }
#pragma unroll
    for (int o = 16; o; o >>= 1) {
        s += __shfl_down_sync(0xffffffffu, s, o);
        d += __shfl_down_sync(0xffffffffu, d, o);
    }
    if (lane == 0) { vs[row] = s; vd[row] = d; }
}

// ---------------- es/ed = x @ v (warp per row) ----------------
__global__ void rowdot_kernel(const float* __restrict__ x,
                              const float* __restrict__ vs, const float* __restrict__ vd,
                              float* __restrict__ es, float* __restrict__ ed, int n) {
    int warp = (blockIdx.x * blockDim.x + threadIdx.x) >> 5;
    int lane = threadIdx.x & 31;
    if (warp >= n) return;
    const float4* row = (const float4*)(x + (size_t)warp * D);
    float s = 0.f, d = 0.f;
#pragma unroll
    for (int i = lane; i < D / 4; i += 32) {
        float4 v = __ldg(row + i);
        float4 a = *(const float4*)(vs + i * 4);
        float4 b = *(const float4*)(vd + i * 4);
        s = fmaf(v.x, a.x, fmaf(v.y, a.y, fmaf(v.z, a.z, fmaf(v.w, a.w, s))));
        d = fmaf(v.x, b.x, fmaf(v.y, b.y, fmaf(v.z, b.z, fmaf(v.w, b.w, d))));
    }
#pragma unroll
    for (int o = 16; o; o >>= 1) {
        s += __shfl_down_sync(0xffffffffu, s, o);
        d += __shfl_down_sync(0xffffffffu, d, o);
    }
    if (lane == 0) { es[warp] = s; ed[warp] = d; }
}

// ---------------- fp32 -> fp16 ----------------
__global__ void split_kernel(const float* __restrict__ x,
                             __half* __restrict__ xh, int total4) {
    int i = blockIdx.x * blockDim.x + threadIdx.x;
    if (i < total4) {
        float4 v = *(const float4*)(x + i * 4);
        __half2* o = (__half2*)(xh + i * 4);
        o[0] = __floats2half2_rn(v.x, v.y);
        o[1] = __floats2half2_rn(v.z, v.w);
    }
}

// ---------------- W[k][n] -> Wt[n][k] fp16 ----------------
__global__ void transpose_kernel(const float* __restrict__ W,
                                 __half* __restrict__ Th) {
    __shared__ float sh[32][33];
    int n0 = blockIdx.x * 32, k0 = blockIdx.y * 32;
    int tx = threadIdx.x, ty = threadIdx.y;
#pragma unroll
    for (int j = 0; j < 32; j += 8)
        sh[ty + j][tx] = W[(size_t)(k0 + ty + j) * D + n0 + tx];
    __syncthreads();
#pragma unroll
    for (int j = 0; j < 32; j += 8)
        Th[(size_t)(n0 + ty + j) * D + k0 + tx] = __float2half(sh[tx][ty + j]);
}

// ---------------- tensor-core GEMM (fp16, 8 warps, 2 CTA/SM) ----------------
// y_off: m-tile offset (for split launches of the same logical GEMM).
#define STAGE_BYTES 32768
#define GEMM_SMEM (2 * STAGE_BYTES)

__global__ __launch_bounds__(256, 2)
void gemm_mma_kernel(const __half* __restrict__ Ah,
                     const __half* __restrict__ Bh,
                     __half* __restrict__ C, int M, int y_off) {
    extern __shared__ __align__(1024) char smem[];
    const uint32_t sb = smem_u32(smem);
    const int tid  = threadIdx.x;
    const int wid  = tid >> 5;
    const int lane = tid & 31;
    const int m0 = (blockIdx.y + y_off) * 128;
    const int n0 = blockIdx.x * 128;
    const int warp_m = (wid & 1) * 64;
    const int warp_n = (wid >> 1) * 32;

    float acc[4][4][4];
#pragma unroll
    for (int i = 0; i < 4; i++)
#pragma unroll
        for (int j = 0; j < 4; j++)
#pragma unroll
            for (int k = 0; k < 4; k++) acc[i][j][k] = 0.f;

    auto issue_chunk = [&](int c) {
        const uint32_t st = sb + (uint32_t)(c & 1) * STAGE_BYTES;
        const int kc0 = c * 64;
#pragma unroll
        for (int i = 0; i < 4; i++) {
            int idx = i * 256 + tid;
            int row = idx >> 3, cc = idx & 7;
            uint32_t so = sw128((uint32_t)(row * 128 + cc * 16));
            int m = m0 + row; if (m >= M) m = M - 1;   // clamp: rows >= M never stored
            cp_async16(st + 0     + so, Ah + (size_t)m * D + kc0 + cc * 8);
            cp_async16(st + 16384 + so, Bh + (size_t)(n0 + row) * D + kc0 + cc * 8);
        }
    };

    issue_chunk(0);
    asm volatile("cp.async.commit_group;" ::: "memory");

#pragma unroll 1
    for (int c = 0; c < 12; c++) {
        if (c + 1 < 12) {
            issue_chunk(c + 1);
            asm volatile("cp.async.commit_group;" ::: "memory");
            asm volatile("cp.async.wait_group 1;" ::: "memory");
        } else {
            asm volatile("cp.async.wait_group 0;" ::: "memory");
        }
        __syncthreads();

        const uint32_t st = sb + (uint32_t)(c & 1) * STAGE_BYTES;
#pragma unroll
        for (int ks = 0; ks < 4; ks++) {
            uint32_t af[4][4], bf[2][4];
            const int arow = lane & 15;
            const int acol = (ks * 16 + (lane >> 4) * 8) * 2;
#pragma unroll
            for (int mt = 0; mt < 4; mt++) {
                uint32_t off = sw128((uint32_t)((warp_m + mt * 16 + arow) * 128 + acol));
                ldsm4(af[mt], st + off);
            }
            const int brow = (lane & 7) + ((lane >> 4) << 3);
            const int bcol = (ks * 16 + ((lane >> 3) & 1) * 8) * 2;
#pragma unroll
            for (int p = 0; p < 2; p++) {
                uint32_t off = sw128((uint32_t)((warp_n + p * 16 + brow) * 128 + bcol));
                ldsm4(bf[p], st + 16384 + off);
            }
#pragma unroll
            for (int mt = 0; mt < 4; mt++) {
#pragma unroll
                for (int nt = 0; nt < 4; nt++)
                    mma_fp16(acc[mt][nt], af[mt], &bf[nt >> 1][(nt & 1) * 2]);
            }
        }
        __syncthreads();
    }

    const int er = lane >> 2;
    const int ec = (lane & 3) * 2;
#pragma unroll
    for (int mt = 0; mt < 4; mt++) {
        int row = m0 + warp_m + mt * 16 + er;
#pragma unroll
        for (int nt = 0; nt < 4; nt++) {
            int col = n0 + warp_n + nt * 8 + ec;
            if (row < M)
                *(__half2*)(C + (size_t)row * D + col) =
                    __floats2half2_rn(acc[mt][nt][0], acc[mt][nt][1]);
            if (row + 8 < M)
                *(__half2*)(C + (size_t)(row + 8) * D + col) =
                    __floats2half2_rn(acc[mt][nt][2], acc[mt][nt][3]);
        }
    }
}

// ---------------- segment softmax + aggregation (inline edge weights) ------------
// node = blockIdx.x + node_off. MODE 0: fp32 out + bias. MODE 1: relu -> fp16 + logits.
template <int MODE>
__global__ __launch_bounds__(384)
void agg_kernel(const __half* __restrict__ h, const float* __restrict__ bias,
                const float* __restrict__ es, const float* __restrict__ ed,
                const float* __restrict__ v2s, const float* __restrict__ v2d,
                float* __restrict__ es2, float* __restrict__ ed2,
                void* __restrict__ outp, int node_off) {
    const int node = blockIdx.x + node_off;
    const int tid = threadIdx.x;
    const int beg = g_off[node];
    const int end = g_off[node + 1];
    const float edv = ed[node];

    __shared__ float sw[384];
    __shared__ int ssrc[384];

    float z = 0.f, ax = 0.f, ay = 0.f;
    for (int base = beg; base < end; base += 384) {
        int cnt = min(384, end - base);
        if (tid < cnt) {
            int s = __ldg(&g_csr_src[base + tid]);
            ssrc[tid] = s;
            float e = __ldg(&es[s]) + edv;
            e = (e > 0.f) ? e : 0.2f * e;
            sw[tid] = expf(e);
        }
        __syncthreads();
        for (int j = 0; j < cnt; j++) {
            float w = sw[j];
            z += w;
            __half2 hv = __ldg((const __half2*)(h + (size_t)ssrc[j] * D) + tid);
            float2 hf = __half22float2(hv);
            ax = fmaf(w, hf.x, ax);
            ay = fmaf(w, hf.y, ay);
        }
        __syncthreads();
    }
    float inv = 1.f / z;
    float ox = ax * inv + bias[2 * tid];
    float oy = ay * inv + bias[2 * tid + 1];
    if (MODE == 1) {
        ox = fmaxf(ox, 0.f);
        oy = fmaxf(oy, 0.f);
        ((__half2*)outp)[(size_t)node * (D / 2) + tid] = __floats2half2_rn(ox, oy);
        float ps = ox * __ldg(&v2s[2 * tid]) + oy * __ldg(&v2s[2 * tid + 1]);
        float pd = ox * __ldg(&v2d[2 * tid]) + oy * __ldg(&v2d[2 * tid + 1]);
#pragma unroll
        for (int o = 16; o; o >>= 1) {
            ps += __shfl_down_sync(0xffffffffu, ps, o);
            pd += __shfl_down_sync(0xffffffffu, pd, o);
        }
        __shared__ float wrs[12], wrd[12];
        int wid = tid >> 5, lane = tid & 31;
        if (lane == 0) { wrs[wid] = ps; wrd[wid] = pd; }
        __syncthreads();
        if (tid == 0) {
            float a = 0.f, b = 0.f;
#pragma unroll
            for (int j = 0; j < 12; j++) { a += wrs[j]; b += wrd[j]; }
            es2[node] = a;
            ed2[node] = b;
        }
    } else {
        ((float2*)outp)[(size_t)node * (D / 2) + tid] = make_float2(ox, oy);
    }
}

// ---------------- launch ----------------
extern "C" void kernel_launch(void* const* d_in, const int* in_sizes, int n_in,
                              void* d_out, int out_size) {
    const float* x   = (const float*)d_in[0];
    const int*   ei  = (const int*)  d_in[1];
    const float* W1  = (const float*)d_in[2];
    const float* as1 = (const float*)d_in[3];
    const float* ad1 = (const float*)d_in[4];
    const float* b1  = (const float*)d_in[5];
    const float* W2  = (const float*)d_in[6];
    const float* as2 = (const float*)d_in[7];
    const float* ad2 = (const float*)d_in[8];
    const float* b2  = (const float*)d_in[9];
    float* out = (float*)d_out;

    const int n     = in_sizes[0] / D;
    const int e_raw = in_sizes[1] / 2;
    const int e_tot = e_raw + n;

    float *es1, *ed1, *es2, *ed2, *v1s, *v1d, *v2s, *v2d;
    __half *h1, *h2, *xh, *gh, *w1h, *w2h;
    cudaGetSymbolAddress((void**)&h1,  g_h1);
    cudaGetSymbolAddress((void**)&h2,  g_h2);
    cudaGetSymbolAddress((void**)&es1, g_es1);
    cudaGetSymbolAddress((void**)&ed1, g_ed1);
    cudaGetSymbolAddress((void**)&es2, g_es2);
    cudaGetSymbolAddress((void**)&ed2, g_ed2);
    cudaGetSymbolAddress((void**)&v1s, g_v1s);
    cudaGetSymbolAddress((void**)&v1d, g_v1d);
    cudaGetSymbolAddress((void**)&v2s, g_v2s);
    cudaGetSymbolAddress((void**)&v2d, g_v2d);
    cudaGetSymbolAddress((void**)&xh,  g_xh);
    cudaGetSymbolAddress((void**)&gh,  g_gh);
    cudaGetSymbolAddress((void**)&w1h, g_w1h);
    cudaGetSymbolAddress((void**)&w2h, g_w2h);

    cudaFuncSetAttribute(gemm_mma_kernel, cudaFuncAttributeMaxDynamicSharedMemorySize, GEMM_SMEM);

    static cudaStream_t s_side = nullptr;
    static cudaEvent_t  e_fork = nullptr, e_csr = nullptr, e_aggA = nullptr, e_g2a = nullptr;
    if (!s_side) {
        if (cudaStreamCreateWithFlags(&s_side, cudaStreamNonBlocking) != cudaSuccess)
            s_side = nullptr;
        cudaEventCreateWithFlags(&e_fork, cudaEventDisableTiming);
        cudaEventCreateWithFlags(&e_csr, cudaEventDisableTiming);
        cudaEventCreateWithFlags(&e_aggA, cudaEventDisableTiming);
        cudaEventCreateWithFlags(&e_g2a, cudaEventDisableTiming);
    }
    cudaStream_t cs = s_side ? s_side : (cudaStream_t)0;

    if (s_side) {
        cudaEventRecord(e_fork, 0);
        cudaStreamWaitEvent(cs, e_fork, 0);
    }

    dim3 tgrid(D / 32, D / 32);

    // --- side stream: CSR chain + W2 transpose + logit matvecs ---
    zero_kernel<<<(n + 255) / 256, 256, 0, cs>>>(n);
    hist_kernel<<<(e_tot + 255) / 256, 256, 0, cs>>>(ei, e_raw, n);
    scan_kernel<<<1, 1024, 0, cs>>>(n);
    scatter_kernel<<<(e_tot + 255) / 256, 256, 0, cs>>>(ei, e_raw, n);
    transpose_kernel<<<tgrid, dim3(32, 8), 0, cs>>>(W2, w2h);
    vcalc_kernel<<<D / 8, 256, 0, cs>>>(W1, as1, ad1, v1s, v1d);
    vcalc_kernel<<<D / 8, 256, 0, cs>>>(W2, as2, ad2, v2s, v2d);
    rowdot_kernel<<<(n + 7) / 8, 256, 0, cs>>>(x, v1s, v1d, es1, ed1, n);
    if (s_side) cudaEventRecord(e_csr, cs);

    // --- main stream: x split + W1 transpose -> GEMM1 ---
    split_kernel<<<(n * D / 4 + 255) / 256, 256>>>(x, xh, n * D / 4);
    transpose_kernel<<<tgrid, dim3(32, 8)>>>(W1, w1h);

    const int tiles_total = (n + 127) / 128;
    const int tilesA = (tiles_total > 40 && s_side) ? 40 : tiles_total;
    const int tilesB = tiles_total - tilesA;
    const int nA = (tilesA * 128 < n) ? tilesA * 128 : n;
    const int nB = n - nA;

    gemm_mma_kernel<<<dim3(D / 128, tiles_total), 256, GEMM_SMEM>>>(xh, w1h, h1, n, 0);

    // join: agg1 needs CSR + es1/ed1 + v2 (side stream)
    if (s_side) cudaStreamWaitEvent((cudaStream_t)0, e_csr, 0);

    // --- layer 1 aggregation, part A (nodes [0, nA)) ---
    agg_kernel<1><<<nA, 384>>>(h1, b1, es1, ed1, v2s, v2d, es2, ed2, gh, 0);

    if (s_side && tilesB > 0) {
        // GEMM2_A on side stream (m-tiles [0, tilesA)) — needs only gh rows [0, nA)
        cudaEventRecord(e_aggA, 0);
        cudaStreamWaitEvent(cs, e_aggA, 0);
        gemm_mma_kernel<<<dim3(D / 128, tilesA), 256, GEMM_SMEM, cs>>>(gh, w2h, h2, n, 0);
        cudaEventRecord(e_g2a, cs);

        // agg1 part B on main, concurrent with GEMM2_A
        agg_kernel<1><<<nB, 384>>>(h1, b1, es1, ed1, v2s, v2d, es2, ed2, gh, nA);

        // GEMM2_B on main (m-tiles [tilesA, tiles_total))
        gemm_mma_kernel<<<dim3(D / 128, tilesB), 256, GEMM_SMEM>>>(gh, w2h, h2, n, tilesA);

        // agg2 needs all of h2 (GEMM2_A on side + GEMM2_B on main)
        cudaStreamWaitEvent((cudaStream_t)0, e_g2a, 0);
    } else {
        if (nB > 0)
            agg_kernel<1><<<nB, 384>>>(h1, b1, es1, ed1, v2s, v2d, es2, ed2, gh, nA);
        gemm_mma_kernel<<<dim3(D / 128, tiles_total), 256, GEMM_SMEM>>>(gh, w2h, h2, n, 0);
    }

    // --- layer 2 aggregation -> final output ---
    agg_kernel<0><<<n, 384>>>(h2, b2, es2, ed2, nullptr, nullptr, nullptr, nullptr, out, 0);
}